// round 8
// baseline (speedup 1.0000x reference)
#include <cuda_runtime.h>
#include <cuda_bf16.h>
#include <stdint.h>

// ---------------- problem constants ----------------
#define N_NODES 16384
#define NE      524288
#define IN_F    128
#define OUT_F   64

// ---------------- device scratch ----------------
__device__ float         g_hw [N_NODES * OUT_F];   // 4 MB
__device__ float         g_agg[N_NODES * OUT_F];   // 4 MB
__device__ float         g_u  [N_NODES * OUT_F];   // 4 MB (dropout uniforms)
__device__ __nv_bfloat16 g_xhi[N_NODES * OUT_F];   // 2 MB
__device__ __nv_bfloat16 g_xlo[N_NODES * OUT_F];   // 2 MB
__device__ int           g_is64;

// ---------------- launch 1: int-width detect ----------------
__global__ void detect_kernel(const unsigned int* __restrict__ w) {
    __shared__ int cnt;
    if (threadIdx.x == 0) cnt = 0;
    __syncthreads();
    int z = 0;
    for (int i = threadIdx.x; i < 1024; i += 256)
        z += (w[2 * i + 1] == 0u) ? 1 : 0;
    atomicAdd(&cnt, z);
    __syncthreads();
    if (threadIdx.x == 0) g_is64 = (cnt > 512) ? 1 : 0;
}

// ---------------- launch 2: fused proj + zero(agg) ----------------
__global__ __launch_bounds__(256) void k_fused2(const float* __restrict__ h,
                                                const float* __restrict__ W) {
    int bid = blockIdx.x;
    int tid = threadIdx.x;
    if (bid < 2048) {
        __shared__ float sW[IN_F * OUT_F];  // 32 KB
        __shared__ float sH[8][IN_F];       // 4 KB
        int wid = tid >> 5, lid = tid & 31;
        for (int i = tid; i < IN_F * OUT_F; i += 256) sW[i] = W[i];
        int r = bid * 8 + wid;
        #pragma unroll
        for (int t = 0; t < 4; t++) sH[wid][lid + 32 * t] = h[(size_t)r * IN_F + lid + 32 * t];
        __syncthreads();
        float a0 = 0.f, a1 = 0.f;
        #pragma unroll
        for (int k = 0; k < IN_F; k++) {
            float hv = sH[wid][k];
            a0 += hv * sW[k * OUT_F + lid];
            a1 += hv * sW[k * OUT_F + lid + 32];
        }
        g_hw[r * OUT_F + lid]      = a0;
        g_hw[r * OUT_F + lid + 32] = a1;
    } else {
        int i = (bid - 2048) * 256 + tid;
        g_agg[i] = 0.f;
    }
}

// ---------------- threefry2x32 (JAX-exact, 20 rounds) ----------------
__device__ __forceinline__ void threefry2x32(uint32_t k0, uint32_t k1,
                                             uint32_t x0, uint32_t x1,
                                             uint32_t& o0, uint32_t& o1) {
    uint32_t ks0 = k0, ks1 = k1, ks2 = 0x1BD11BDAu ^ k0 ^ k1;
    x0 += ks0; x1 += ks1;
#define TF_R(rr) { x0 += x1; x1 = (x1 << (rr)) | (x1 >> (32 - (rr))); x1 ^= x0; }
    TF_R(13) TF_R(15) TF_R(26) TF_R(6)  x0 += ks1; x1 += ks2 + 1u;
    TF_R(17) TF_R(29) TF_R(16) TF_R(24) x0 += ks2; x1 += ks0 + 2u;
    TF_R(13) TF_R(15) TF_R(26) TF_R(6)  x0 += ks0; x1 += ks1 + 3u;
    TF_R(17) TF_R(29) TF_R(16) TF_R(24) x0 += ks1; x1 += ks2 + 4u;
    TF_R(13) TF_R(15) TF_R(26) TF_R(6)  x0 += ks2; x1 += ks0 + 5u;
#undef TF_R
    o0 = x0; o1 = x1;
}

// ---------------- launch 3: dropout uniforms (data-independent, moved early) ----------------
__global__ __launch_bounds__(256) void k_masku() {
    int i = blockIdx.x * 256 + threadIdx.x;
    uint32_t o0, o1;
    threefry2x32(0u, 42u, 0u, (uint32_t)i, o0, o1);
    uint32_t bits = o0 ^ o1;
    g_u[i] = __uint_as_float((bits >> 9) | 0x3f800000u) - 1.0f;
}

// ---------------- launch 4 (ncu target): scatter, 2 edges per 16-lane group ----------------
__global__ __launch_bounds__(256) void k2_scatter(const unsigned int* __restrict__ srcw,
                                                  const unsigned int* __restrict__ dstw) {
    unsigned g = (blockIdx.x * 256u + threadIdx.x) >> 4;   // edge-pair id < NE/2
    int sub = threadIdx.x & 15;
    unsigned s0, s1, d0, d1;
    if (!g_is64) {
        uint2 sv = *(const uint2*)&srcw[2 * (size_t)g];
        uint2 dv = *(const uint2*)&dstw[2 * (size_t)g];
        s0 = sv.x; s1 = sv.y; d0 = dv.x; d1 = dv.y;
    } else {
        uint4 sv = *(const uint4*)&srcw[4 * (size_t)g];
        uint4 dv = *(const uint4*)&dstw[4 * (size_t)g];
        s0 = sv.x; s1 = sv.z; d0 = dv.x; d1 = dv.z;
    }
    const float4* src = (const float4*)g_hw;
    float4 v0 = src[s0 * 16 + sub];
    asm volatile("red.global.add.v4.f32 [%0], {%1,%2,%3,%4};"
                 :: "l"(&g_agg[d0 * OUT_F + sub * 4]),
                    "f"(v0.x), "f"(v0.y), "f"(v0.z), "f"(v0.w) : "memory");
    float4 v1 = src[s1 * 16 + sub];
    asm volatile("red.global.add.v4.f32 [%0], {%1,%2,%3,%4};"
                 :: "l"(&g_agg[d1 * OUT_F + sub * 4]),
                    "f"(v1.x), "f"(v1.y), "f"(v1.z), "f"(v1.w) : "memory");
}

// ---------------- launch 5: apply relu+dropout+split (vectorized) ----------------
__global__ __launch_bounds__(256) void k3_apply(const float* __restrict__ bias) {
    int idx = (blockIdx.x * 256 + threadIdx.x) * 4;   // 4 elems/thread
    float4 a = *(const float4*)&g_agg[idx];
    float4 u = *(const float4*)&g_u[idx];
    float4 b = *(const float4*)&bias[idx & 63];
    float y0 = (u.x < 0.7f) ? fmaxf(a.x + b.x, 0.f) / 0.7f : 0.f;
    float y1 = (u.y < 0.7f) ? fmaxf(a.y + b.y, 0.f) / 0.7f : 0.f;
    float y2 = (u.z < 0.7f) ? fmaxf(a.z + b.z, 0.f) / 0.7f : 0.f;
    float y3 = (u.w < 0.7f) ? fmaxf(a.w + b.w, 0.f) / 0.7f : 0.f;
    __nv_bfloat16 h0 = __float2bfloat16(y0), h1 = __float2bfloat16(y1);
    __nv_bfloat16 h2 = __float2bfloat16(y2), h3 = __float2bfloat16(y3);
    __nv_bfloat162 hp0(h0, h1), hp1(h2, h3);
    __nv_bfloat162 lp0(__float2bfloat16(y0 - __bfloat162float(h0)),
                       __float2bfloat16(y1 - __bfloat162float(h1)));
    __nv_bfloat162 lp1(__float2bfloat16(y2 - __bfloat162float(h2)),
                       __float2bfloat16(y3 - __bfloat162float(h3)));
    *(uint2*)&g_xhi[idx] = make_uint2(*(uint32_t*)&hp0, *(uint32_t*)&hp1);
    *(uint2*)&g_xlo[idx] = make_uint2(*(uint32_t*)&lp0, *(uint32_t*)&lp1);
}

// ---------------- launch 6: out = x @ x^T, symmetric (write-floored ~299us) ----------------
#define SM_AHI  0
#define SM_ALO  16384
#define SM_BHI  32768
#define SM_BLO  49152
#define STAGE_STRIDE 136
#define SM_TOTAL (128 * STAGE_STRIDE * 4)   // 69632 B

__device__ __forceinline__ void ldsm_x4(uint32_t* r, uint32_t addr) {
    asm volatile("ldmatrix.sync.aligned.m8n8.x4.shared.b16 {%0,%1,%2,%3}, [%4];"
                 : "=r"(r[0]), "=r"(r[1]), "=r"(r[2]), "=r"(r[3]) : "r"(addr));
}
__device__ __forceinline__ void mma16816(float* d, const uint32_t* a,
                                         uint32_t b0, uint32_t b1) {
    asm volatile(
        "mma.sync.aligned.m16n8k16.row.col.f32.bf16.bf16.f32 "
        "{%0,%1,%2,%3}, {%4,%5,%6,%7}, {%8,%9}, {%0,%1,%2,%3};"
        : "+f"(d[0]), "+f"(d[1]), "+f"(d[2]), "+f"(d[3])
        : "r"(a[0]), "r"(a[1]), "r"(a[2]), "r"(a[3]), "r"(b0), "r"(b1));
}
__device__ __forceinline__ void stg_cs(float* p, float4 v) {
    asm volatile("st.global.cs.v4.f32 [%0], {%1,%2,%3,%4};"
                 :: "l"(p), "f"(v.x), "f"(v.y), "f"(v.z), "f"(v.w) : "memory");
}
__device__ __forceinline__ void cp_async16(uint32_t saddr, const void* gptr) {
    asm volatile("cp.async.cg.shared.global [%0], [%1], 16;"
                 :: "r"(saddr), "l"(gptr) : "memory");
}

__global__ __launch_bounds__(512, 2)
void k4_gemm(float* __restrict__ out) {
    extern __shared__ char smem[];
    uint32_t sb = (uint32_t)__cvta_generic_to_shared(smem);
    int tid = threadIdx.x, wid = tid >> 5, lid = tid & 31;
    int wm = wid & 3, wn = wid >> 2;   // 4x4 warp grid, warp tile 32x32

    int bid = blockIdx.x;
    int ti = (int)((257.0 - sqrt(66049.0 - 8.0 * (double)bid)) * 0.5);
    while ((ti + 1) * 128 - ((ti + 1) * ti) / 2 <= bid) ti++;
    while (ti * 128 - (ti * (ti - 1)) / 2 > bid) ti--;
    int tj = ti + (bid - (ti * 128 - (ti * (ti - 1)) / 2));
    int rowA = ti << 7;
    int rowB = tj << 7;

    {
        const __nv_bfloat16* bases[4] = {
            g_xhi + (size_t)rowA * OUT_F, g_xlo + (size_t)rowA * OUT_F,
            g_xhi + (size_t)rowB * OUT_F, g_xlo + (size_t)rowB * OUT_F };
        const int offs[4] = { SM_AHI, SM_ALO, SM_BHI, SM_BLO };
        #pragma unroll
        for (int t = 0; t < 4; t++) {
            const char* gp = (const char*)bases[t];
            #pragma unroll
            for (int j = 0; j < 2; j++) {
                int idx = tid + j * 512;
                uint32_t bo = (uint32_t)(idx << 4);
                uint32_t sw = bo ^ ((bo >> 3) & 0x70);
                cp_async16(sb + offs[t] + sw, gp + ((size_t)idx << 4));
            }
        }
        asm volatile("cp.async.commit_group;" ::: "memory");
        asm volatile("cp.async.wait_group 0;" ::: "memory");
    }
    __syncthreads();

    float acc[2][4][4];
    #pragma unroll
    for (int mt = 0; mt < 2; mt++)
        #pragma unroll
        for (int nt = 0; nt < 4; nt++)
            #pragma unroll
            for (int e = 0; e < 4; e++) acc[mt][nt][e] = 0.f;

    int lrow = lid & 15;
    int lchk = lid >> 4;
    int lswz = lid & 7;

    #pragma unroll
    for (int kc = 0; kc < 4; kc++) {
        uint32_t chunk = (uint32_t)(((2 * kc + lchk) ^ lswz) << 4);
        uint32_t ah[2][4], al[2][4];
        #pragma unroll
        for (int mt = 0; mt < 2; mt++) {
            uint32_t ro = (uint32_t)((wm * 32 + mt * 16 + lrow) * 128) + chunk;
            ldsm_x4(ah[mt], sb + SM_AHI + ro);
            ldsm_x4(al[mt], sb + SM_ALO + ro);
        }
        #pragma unroll
        for (int np = 0; np < 2; np++) {
            uint32_t bh[4], bl[4];
            uint32_t ro = (uint32_t)((wn * 32 + np * 16 + lrow) * 128) + chunk;
            ldsm_x4(bh, sb + SM_BHI + ro);
            ldsm_x4(bl, sb + SM_BLO + ro);
            #pragma unroll
            for (int mt = 0; mt < 2; mt++)
                #pragma unroll
                for (int sel = 0; sel < 2; sel++) {
                    int nt = np * 2 + sel;
                    mma16816(acc[mt][nt], ah[mt], bh[sel], bh[sel + 2]); // hi*hi
                    mma16816(acc[mt][nt], ah[mt], bl[sel], bl[sel + 2]); // hi*lo
                    mma16816(acc[mt][nt], al[mt], bh[sel], bh[sel + 2]); // lo*hi
                }
        }
    }
    __syncthreads();

    float* stage = (float*)smem;    // [128][STAGE_STRIDE]
    int gid = lid >> 2, tig = lid & 3;

    // pass 1: direct tile
    #pragma unroll
    for (int mt = 0; mt < 2; mt++)
        #pragma unroll
        for (int half = 0; half < 2; half++) {
            int r = wm * 32 + mt * 16 + gid + 8 * half;
            #pragma unroll
            for (int nt = 0; nt < 4; nt++) {
                int c = wn * 32 + nt * 8 + tig * 2;
                *(float2*)&stage[r * STAGE_STRIDE + c] =
                    make_float2(acc[mt][nt][half * 2], acc[mt][nt][half * 2 + 1]);
            }
        }
    __syncthreads();
    {
        size_t obase = (size_t)rowA * 16384 + rowB;
        #pragma unroll
        for (int it = 0; it < 8; it++) {
            int r = it * 16 + wid;
            float4 v = *(float4*)&stage[r * STAGE_STRIDE + lid * 4];
            stg_cs(out + obase + (size_t)r * 16384 + lid * 4, v);
        }
    }

    // pass 2: transposed tile (skip on diagonal)
    if (ti != tj) {
        __syncthreads();
        #pragma unroll
        for (int mt = 0; mt < 2; mt++)
            #pragma unroll
            for (int half = 0; half < 2; half++) {
                int r = wm * 32 + mt * 16 + gid + 8 * half;
                #pragma unroll
                for (int nt = 0; nt < 4; nt++) {
                    int c = wn * 32 + nt * 8 + tig * 2;
                    stage[c * STAGE_STRIDE + r]       = acc[mt][nt][half * 2];
                    stage[(c + 1) * STAGE_STRIDE + r] = acc[mt][nt][half * 2 + 1];
                }
            }
        __syncthreads();
        size_t obase = (size_t)rowB * 16384 + rowA;
        #pragma unroll
        for (int it = 0; it < 8; it++) {
            int r = it * 16 + wid;
            float4 v = *(float4*)&stage[r * STAGE_STRIDE + lid * 4];
            stg_cs(out + obase + (size_t)r * 16384 + lid * 4, v);
        }
    }
}

// ---------------- launch ----------------
extern "C" void kernel_launch(void* const* d_in, const int* in_sizes, int n_in,
                              void* d_out, int out_size) {
    const float*        h    = (const float*)d_in[0];
    const unsigned int* srcw = (const unsigned int*)d_in[1];
    const unsigned int* dstw = (const unsigned int*)d_in[2];
    const float*        W    = (const float*)d_in[3];
    const float*        bias = (const float*)d_in[4];
    float*              out  = (float*)d_out;

    detect_kernel<<<1, 256>>>(srcw);                        // 1
    k_fused2<<<6144, 256>>>(h, W);                          // 2
    k_masku<<<(N_NODES * OUT_F) / 256, 256>>>();            // 3
    k2_scatter<<<(NE / 2 * 16) / 256, 256>>>(srcw, dstw);   // 4  (ncu target)
    k3_apply<<<(N_NODES * OUT_F) / (256 * 4), 256>>>(bias); // 5

    cudaFuncSetAttribute(k4_gemm, cudaFuncAttributeMaxDynamicSharedMemorySize, SM_TOTAL);
    k4_gemm<<<(128 * 129) / 2, 512, SM_TOTAL>>>(out);       // 6
}